// round 1
// baseline (speedup 1.0000x reference)
#include <cuda_runtime.h>
#include <math.h>

#define IMAGE_W 256
#define IMAGE_H 256
#define EPS 1e-7f
#define SIGMA2 0.02f

#define B 16
#define N 64
#define C 3
#define PH 32
#define PW 32
#define LW 33            // splat tile is 33x33
#define LSZ (LW*LW)      // 1089

// Scratch: per-stroke splatted local tiles L[b][n][c][33][33], plus window origins.
__device__ float g_L[B * N * C * LSZ];     // ~13.4 MB
__device__ int   g_fx0[B * N];
__device__ int   g_fy0[B * N];

// ---------------------------------------------------------------------------
// Kernel 1: per-stroke bilinear splat of the 3x32x32 patch into 3x33x33.
// One block per (b, n). 256 threads.
// ---------------------------------------------------------------------------
__global__ void __launch_bounds__(256) splat_kernel(
    const float* __restrict__ brushes,   // [B, N, 2]
    const float* __restrict__ patches)   // [B, N, 3, 32, 32]
{
    const int bn = blockIdx.x;
    const int b  = bn >> 6;
    const int n  = bn & 63;
    const int tid = threadIdx.x;

    __shared__ float sbx[N], sby[N];
    __shared__ float sP[C * PH * PW];   // 12 KB

    if (tid < N) {
        sbx[tid] = brushes[(b * N + tid) * 2 + 0];
        sby[tid] = brushes[(b * N + tid) * 2 + 1];
    }
    const float* P = patches + (size_t)bn * (C * PH * PW);
    for (int i = tid; i < C * PH * PW; i += blockDim.x) sP[i] = P[i];
    __syncthreads();

    // Per-batch min/max over the 64 strokes (redundant per thread; trivial cost).
    float mnx = sbx[0], mxx = sbx[0], mny = sby[0], mxy = sby[0];
#pragma unroll
    for (int k = 1; k < N; k++) {
        mnx = fminf(mnx, sbx[k]); mxx = fmaxf(mxx, sbx[k]);
        mny = fminf(mny, sby[k]); mxy = fmaxf(mxy, sby[k]);
    }

    const float gx = (sbx[n] - mnx) / (mxx - mnx + EPS) * (float)IMAGE_W;
    const float gy = (sby[n] - mny) / (mxy - mny + EPS) * (float)IMAGE_H;

    // ux(q) = gx + q - 15.5  -> constant fractional part across q
    const float axc = gx - 15.5f;
    const float fx0f = floorf(axc);
    const float dx = axc - fx0f;
    // uy(p) = gy + p - 15.4
    const float ayc = gy - 15.4f;
    const float fy0f = floorf(ayc);
    const float dy = ayc - fy0f;

    const float gx0 = expf(-(dx * dx) / SIGMA2);
    const float gx1 = expf(-((1.0f - dx) * (1.0f - dx)) / SIGMA2);
    const float inv_sx = 1.0f / (gx0 + gx1 + EPS);
    const float wx0 = gx0 * inv_sx;
    const float wx1 = gx1 * inv_sx;

    const float gy0 = expf(-(dy * dy) / SIGMA2);
    const float gy1 = expf(-((1.0f - dy) * (1.0f - dy)) / SIGMA2);
    const float inv_sy = 1.0f / (gy0 + gy1 + EPS);
    const float wy0 = gy0 * inv_sy;
    const float wy1 = gy1 * inv_sy;

    if (tid == 0) {
        g_fx0[bn] = (int)fx0f;
        g_fy0[bn] = (int)fy0f;
    }

    const float scale = 1.0f / 64.0f;  // the /N in the reference
    const float a00 = wy0 * wx0 * scale;
    const float a01 = wy0 * wx1 * scale;
    const float a10 = wy1 * wx0 * scale;
    const float a11 = wy1 * wx1 * scale;

    float* Lp = g_L + (size_t)bn * (C * LSZ);
    for (int idx = tid; idx < C * LSZ; idx += blockDim.x) {
        const int c = idx / LSZ;
        const int r = idx - c * LSZ;
        const int j = r / LW;       // 0..32 (output row)
        const int i = r - j * LW;   // 0..32 (output col)
        float v = 0.0f;
        // L[c,j,i] = sum_{dy,dx in {0,1}} w[dy][dx] * P[c, j-dy, i-dx]
        if (j < PH && i < PW)            v += a00 * sP[(c * PH + j) * PW + i];
        if (j < PH && i >= 1)            v += a01 * sP[(c * PH + j) * PW + (i - 1)];
        if (j >= 1 && i < PW)            v += a10 * sP[(c * PH + (j - 1)) * PW + i];
        if (j >= 1 && i >= 1)            v += a11 * sP[(c * PH + (j - 1)) * PW + (i - 1)];
        Lp[idx] = v;
    }
}

// ---------------------------------------------------------------------------
// Kernel 2: gather. One thread per (b, y, x), accumulating all 3 channels.
// Deterministic n-ascending accumulation (no atomics).
// ---------------------------------------------------------------------------
__global__ void __launch_bounds__(256) gather_kernel(float* __restrict__ out)
{
    const int b = blockIdx.y;
    const int y = blockIdx.x;
    const int x = threadIdx.x;

    __shared__ int sfx[N], sfy[N];
    if (x < N) {
        sfx[x] = g_fx0[b * N + x];
        sfy[x] = g_fy0[b * N + x];
    }
    __syncthreads();

    float a0 = 0.0f, a1 = 0.0f, a2 = 0.0f;
    const float* Lb = g_L + (size_t)b * N * C * LSZ;

#pragma unroll 8
    for (int n = 0; n < N; n++) {
        const int ix = x - sfx[n];
        const int iy = y - sfy[n];
        if ((unsigned)ix < (unsigned)LW && (unsigned)iy < (unsigned)LW) {
            const float* Lp = Lb + (size_t)n * (C * LSZ) + iy * LW + ix;
            a0 += Lp[0];
            a1 += Lp[LSZ];
            a2 += Lp[2 * LSZ];
        }
    }

    const size_t o = ((size_t)(b * C) * IMAGE_H + y) * IMAGE_W + x;
    out[o]                         = a0;
    out[o + IMAGE_H * IMAGE_W]     = a1;
    out[o + 2 * IMAGE_H * IMAGE_W] = a2;
}

extern "C" void kernel_launch(void* const* d_in, const int* in_sizes, int n_in,
                              void* d_out, int out_size)
{
    const float* brushes = (const float*)d_in[0];   // [16,64,2]
    const float* patches = (const float*)d_in[1];   // [16,64,3,32,32]
    float* out = (float*)d_out;                     // [16,3,256,256]

    splat_kernel<<<B * N, 256>>>(brushes, patches);
    dim3 grid(IMAGE_H, B);
    gather_kernel<<<grid, IMAGE_W>>>(out);
}

// round 2
// speedup vs baseline: 1.8632x; 1.8632x over previous
#include <cuda_runtime.h>
#include <math.h>

#define IMAGE_W 256
#define IMAGE_H 256
#define EPS 1e-7f
#define SIGMA2 0.02f

#define B 16
#define N 64
#define C 3
#define PH 32
#define PW 32
// Output tiling: 8x8 tiles of 32x32 pixels per batch image.
#define TILE 32

// Fused kernel: one block per (batch, 32x32 tile). 256 threads; each thread
// owns 4 pixels (same x, rows y0+{0,8,16,24}) x 3 channels.
__global__ void __launch_bounds__(256) brush_fused_kernel(
    const float* __restrict__ brushes,   // [B, N, 2]
    const float* __restrict__ patches,   // [B, N, 3, 32, 32]
    float* __restrict__ out)             // [B, 3, 256, 256]
{
    const int b    = blockIdx.y;
    const int tile = blockIdx.x;           // 0..63
    const int tx0  = (tile & 7) * TILE;
    const int ty0  = (tile >> 3) * TILE;
    const int tid  = threadIdx.x;

    __shared__ float  sbx[N], sby[N];
    __shared__ int    sfx[N], sfy[N];
    __shared__ float4 sw[N];               // a00, a01, a10, a11 (pre-scaled by 1/64)
    __shared__ float  sP[C * PH * PW];     // 12 KB staged patch

    // ---- per-stroke window params (threads 0..63) ----
    if (tid < N) {
        sbx[tid] = brushes[(b * N + tid) * 2 + 0];
        sby[tid] = brushes[(b * N + tid) * 2 + 1];
    }
    __syncthreads();

    if (tid < N) {
        float mnx = sbx[0], mxx = sbx[0], mny = sby[0], mxy = sby[0];
#pragma unroll
        for (int k = 1; k < N; k++) {
            mnx = fminf(mnx, sbx[k]); mxx = fmaxf(mxx, sbx[k]);
            mny = fminf(mny, sby[k]); mxy = fmaxf(mxy, sby[k]);
        }
        const float gx = (sbx[tid] - mnx) / (mxx - mnx + EPS) * (float)IMAGE_W;
        const float gy = (sby[tid] - mny) / (mxy - mny + EPS) * (float)IMAGE_H;

        // ux(q) = gx + q - 15.5 : constant fractional part across q
        const float axc = gx - 15.5f;
        const float fx0f = floorf(axc);
        const float dx = axc - fx0f;
        // uy(p) = gy + p - 15.4
        const float ayc = gy - 15.4f;
        const float fy0f = floorf(ayc);
        const float dy = ayc - fy0f;

        const float gx0 = __expf(-(dx * dx) / SIGMA2);
        const float gx1 = __expf(-((1.0f - dx) * (1.0f - dx)) / SIGMA2);
        const float wx0 = gx0 / (gx0 + gx1 + EPS);
        const float wx1 = gx1 / (gx0 + gx1 + EPS);

        const float gy0 = __expf(-(dy * dy) / SIGMA2);
        const float gy1 = __expf(-((1.0f - dy) * (1.0f - dy)) / SIGMA2);
        const float wy0 = gy0 / (gy0 + gy1 + EPS);
        const float wy1 = gy1 / (gy0 + gy1 + EPS);

        sfx[tid] = (int)fx0f;
        sfy[tid] = (int)fy0f;
        const float s = 1.0f / 64.0f;      // the /N
        sw[tid] = make_float4(wy0 * wx0 * s, wy0 * wx1 * s,
                              wy1 * wx0 * s, wy1 * wx1 * s);
    }
    __syncthreads();

    // ---- this thread's pixels ----
    const int lx   = tid & 31;             // x within tile
    const int lyb  = tid >> 5;             // base row 0..7 (rows lyb + 8k)
    const int x    = tx0 + lx;

    float acc[4][C];
#pragma unroll
    for (int k = 0; k < 4; k++)
#pragma unroll
        for (int c = 0; c < C; c++) acc[k][c] = 0.0f;

    const float* Pb = patches + (size_t)(b * N) * (C * PH * PW);

    for (int n = 0; n < N; n++) {
        const int fx = sfx[n];
        const int fy = sfy[n];
        // window covers cols [fx, fx+32], rows [fy, fy+32] (33 wide)
        // block-uniform overlap test with this 32x32 tile
        if (fx > tx0 + 31 || fx + 32 < tx0 || fy > ty0 + 31 || fy + 32 < ty0)
            continue;

        // stage the full 3x32x32 patch (768 float4)
        __syncthreads();   // protect previous stroke's sP readers
        {
            const float4* src = (const float4*)(Pb + (size_t)n * (C * PH * PW));
            float4* dst = (float4*)sP;
#pragma unroll
            for (int i = 0; i < 3; i++)
                dst[tid + i * 256] = src[tid + i * 256];
        }
        __syncthreads();

        const int i = x - fx;              // window col, valid 0..32
        if ((unsigned)i > 32u) continue;   // uniform-ish per warp-half; cheap

        const float4 w = sw[n];
        const bool ci0 = (i <= 31);        // P[.][i]   valid
        const bool ci1 = (i >= 1);         // P[.][i-1] valid

#pragma unroll
        for (int k = 0; k < 4; k++) {
            const int y = ty0 + lyb + k * 8;
            const int j = y - fy;          // window row, valid 0..32
            if ((unsigned)j > 32u) continue;
            const bool rj0 = (j <= 31);    // P[j][.]   valid
            const bool rj1 = (j >= 1);     // P[j-1][.] valid
#pragma unroll
            for (int c = 0; c < C; c++) {
                const float* Pc = sP + c * (PH * PW);
                float v = 0.0f;
                if (rj0 & ci0) v += w.x * Pc[j * PW + i];
                if (rj0 & ci1) v += w.y * Pc[j * PW + (i - 1)];
                if (rj1 & ci0) v += w.z * Pc[(j - 1) * PW + i];
                if (rj1 & ci1) v += w.w * Pc[(j - 1) * PW + (i - 1)];
                acc[k][c] += v;
            }
        }
    }

    // ---- write out: [b][c][y][x], coalesced per row ----
#pragma unroll
    for (int c = 0; c < C; c++) {
        float* oc = out + ((size_t)(b * C + c) * IMAGE_H) * IMAGE_W;
#pragma unroll
        for (int k = 0; k < 4; k++) {
            const int y = ty0 + lyb + k * 8;
            oc[(size_t)y * IMAGE_W + x] = acc[k][c];
        }
    }
}

extern "C" void kernel_launch(void* const* d_in, const int* in_sizes, int n_in,
                              void* d_out, int out_size)
{
    const float* brushes = (const float*)d_in[0];   // [16,64,2]
    const float* patches = (const float*)d_in[1];   // [16,64,3,32,32]
    float* out = (float*)d_out;                     // [16,3,256,256]

    dim3 grid(64, B);
    brush_fused_kernel<<<grid, 256>>>(brushes, patches, out);
}